// round 3
// baseline (speedup 1.0000x reference)
#include <cuda_runtime.h>
#include <math.h>

#define BB   32
#define LQ   512
#define DD   384
#define FF   384
#define MROWS (BB*LQ)      // 16384
#define KDIM  (DD*3)       // 1152
#define LN_EPS 1e-5f

// Scratch (no allocations allowed).
__device__ float g_buf1[(size_t)MROWS * FF];   // 25.2 MB
__device__ float g_buf2[(size_t)MROWS * FF];   // 25.2 MB
__device__ float g_w1r[(size_t)FF * KDIM];     // 1.7 MB reordered c1_w
__device__ float g_w2r[(size_t)FF * KDIM];     // 1.7 MB reordered c2_w
__device__ int   g_cum[BB * LQ];

// ---------------------------------------------------------------------------
// Reorder W: Wr[f][k*384+d] = W[f][d*3+k]   (im2col K-dim becomes k-major)
// ---------------------------------------------------------------------------
__global__ __launch_bounds__(256) void reorder_w_kernel(
    const float* __restrict__ W, float* __restrict__ Wr)
{
    const int f = blockIdx.x;
    for (int i = threadIdx.x; i < KDIM; i += 256) {
        const int k = i / DD;
        const int d = i - k * DD;
        Wr[(size_t)f * KDIM + i] = W[(size_t)f * KDIM + d * 3 + k];
    }
}

__device__ __forceinline__ unsigned f2tf(float f)
{
    unsigned r;
    asm("cvt.rna.tf32.f32 %0, %1;" : "=r"(r) : "f"(f));
    return r;
}

__device__ __forceinline__ float4 cvt4(float4 v)
{
    float4 r;
    r.x = __uint_as_float(f2tf(v.x)); r.y = __uint_as_float(f2tf(v.y));
    r.z = __uint_as_float(f2tf(v.z)); r.w = __uint_as_float(f2tf(v.w));
    return r;
}

__device__ __forceinline__ void mma_tf32(float c[4], const unsigned a[4],
                                         const unsigned b[2])
{
    asm volatile(
        "mma.sync.aligned.m16n8k8.row.col.f32.tf32.tf32.f32 "
        "{%0,%1,%2,%3}, {%4,%5,%6,%7}, {%8,%9}, {%0,%1,%2,%3};"
        : "+f"(c[0]), "+f"(c[1]), "+f"(c[2]), "+f"(c[3])
        : "r"(a[0]), "r"(a[1]), "r"(a[2]), "r"(a[3]), "r"(b[0]), "r"(b[1]));
}

// ---------------------------------------------------------------------------
// Conv-as-GEMM on tensor cores (tf32 mma.sync), implicit im2col, k-major K.
// CTA tile 128x128, BK=16, 128 threads, warp grid 2(m) x 2(n), warp tile 64x64.
// Double-buffered smem with register-staged prefetch; stride-20 rows keep all
// fragment LDS and all loader STS.128 conflict-free.
// ---------------------------------------------------------------------------
__global__ __launch_bounds__(128, 2) void conv_mma_kernel(
    const float* __restrict__ X, const float* __restrict__ Wr,
    const float* __restrict__ bias, float* __restrict__ Y)
{
    __shared__ float As[2][128][20];
    __shared__ float Bs[2][128][20];

    const int m0 = blockIdx.x * 128;
    const int f0 = blockIdx.y * 128;
    const int t  = threadIdx.x;

    const int lane = t & 31;
    const int grp  = lane >> 2;     // 0..7
    const int tig  = lane & 3;      // 0..3
    const int warp = t >> 5;        // 0..3
    const int m_base = (warp & 1) * 64;
    const int n_base = (warp >> 1) * 64;

    // loader mapping: row = lane + rr*32, quad(col4) = warp*4
    const int lrow  = lane;
    const int lcol4 = warp * 4;

    int bA[4], lA[4];
    #pragma unroll
    for (int rr = 0; rr < 4; ++rr) {
        const int m = m0 + lrow + rr * 32;
        bA[rr] = m >> 9;
        lA[rr] = m & 511;
    }

    float acc[4][8][4] = {};

    // ---- preload iter 0 into buffer 0 ----
    {
        #pragma unroll
        for (int rr = 0; rr < 4; ++rr) {
            const int row = lrow + rr * 32;
            const int l2  = lA[rr] - 1;               // kseg=0
            float4 pa = make_float4(0,0,0,0);
            if (l2 >= 0)
                pa = *(const float4*)&X[((size_t)(bA[rr] << 9) + l2) * DD + lcol4];
            *(float4*)&As[0][row][lcol4] = cvt4(pa);
            float4 pb = *(const float4*)&Wr[(size_t)(f0 + row) * KDIM + lcol4];
            *(float4*)&Bs[0][row][lcol4] = cvt4(pb);
        }
    }
    __syncthreads();

    const int NIT = KDIM / 16;   // 72
    for (int it = 0; it < NIT; ++it) {
        const bool has = (it + 1 < NIT);
        float4 pa[4], pb[4];

        if (has) {
            const int kk0  = (it + 1) * 16;
            const int kseg = (kk0 >= 384) + (kk0 >= 768);
            const int d0   = kk0 - kseg * DD + lcol4;
            #pragma unroll
            for (int rr = 0; rr < 4; ++rr) {
                const int l2 = lA[rr] + kseg - 1;
                pa[rr] = make_float4(0,0,0,0);
                if (l2 >= 0 && l2 < LQ)
                    pa[rr] = *(const float4*)&X[((size_t)(bA[rr] << 9) + l2) * DD + d0];
                pb[rr] = *(const float4*)&Wr[(size_t)(f0 + lrow + rr * 32) * KDIM + kk0 + lcol4];
            }
        }

        // ---- compute on buffer it&1 ----
        const int buf = it & 1;
        #pragma unroll
        for (int ks = 0; ks < 2; ++ks) {
            const int col = ks * 8 + tig;
            unsigned bf[8][2];
            #pragma unroll
            for (int nt = 0; nt < 8; ++nt) {
                const int br = n_base + nt * 8 + grp;
                bf[nt][0] = __float_as_uint(Bs[buf][br][col]);
                bf[nt][1] = __float_as_uint(Bs[buf][br][col + 4]);
            }
            #pragma unroll
            for (int mt = 0; mt < 4; ++mt) {
                const int ar = m_base + mt * 16 + grp;
                unsigned af[4];
                af[0] = __float_as_uint(As[buf][ar][col]);
                af[1] = __float_as_uint(As[buf][ar + 8][col]);
                af[2] = __float_as_uint(As[buf][ar][col + 4]);
                af[3] = __float_as_uint(As[buf][ar + 8][col + 4]);
                #pragma unroll
                for (int nt = 0; nt < 8; ++nt)
                    mma_tf32(acc[mt][nt], af, bf[nt]);
            }
        }

        if (has) {
            const int nb = (it + 1) & 1;
            #pragma unroll
            for (int rr = 0; rr < 4; ++rr) {
                const int row = lrow + rr * 32;
                *(float4*)&As[nb][row][lcol4] = cvt4(pa[rr]);
                *(float4*)&Bs[nb][row][lcol4] = cvt4(pb[rr]);
            }
        }
        __syncthreads();
    }

    // ---- epilogue: bias + store ----
    #pragma unroll
    for (int mt = 0; mt < 4; ++mt) {
        const int mrow = m0 + m_base + mt * 16 + grp;
        #pragma unroll
        for (int nt = 0; nt < 8; ++nt) {
            const int fc = f0 + n_base + nt * 8 + 2 * tig;
            const float b0v = bias[fc], b1v = bias[fc + 1];
            float2 r0 = make_float2(acc[mt][nt][0] + b0v, acc[mt][nt][1] + b1v);
            float2 r1 = make_float2(acc[mt][nt][2] + b0v, acc[mt][nt][3] + b1v);
            *(float2*)&Y[(size_t)mrow * FF + fc] = r0;
            *(float2*)&Y[(size_t)(mrow + 8) * FF + fc] = r1;
        }
    }
}

// ---------------------------------------------------------------------------
__device__ __forceinline__ float2 block_reduce2(float s, float q)
{
    __shared__ float sh[8];
    __syncthreads();
    const int lane = threadIdx.x & 31;
    const int w    = threadIdx.x >> 5;
    #pragma unroll
    for (int o = 16; o > 0; o >>= 1) {
        s += __shfl_down_sync(0xffffffffu, s, o);
        q += __shfl_down_sync(0xffffffffu, q, o);
    }
    if (lane == 0) { sh[w] = s; sh[4 + w] = q; }
    __syncthreads();
    if (threadIdx.x == 0) {
        sh[0] = sh[0] + sh[1] + sh[2] + sh[3];
        sh[4] = sh[4] + sh[5] + sh[6] + sh[7];
    }
    __syncthreads();
    return make_float2(sh[0], sh[4]);
}

__global__ __launch_bounds__(128) void ln_relu_kernel(
    const float* __restrict__ In, const float* __restrict__ gam,
    const float* __restrict__ bet, float* __restrict__ Out)
{
    const int row = blockIdx.x;
    const int t   = threadIdx.x;
    const float* p = In + (size_t)row * FF;
    float v0 = p[t], v1 = p[t + 128], v2 = p[t + 256];
    float2 r = block_reduce2(v0 + v1 + v2, v0 * v0 + v1 * v1 + v2 * v2);
    const float mu  = r.x * (1.0f / FF);
    const float var = r.y * (1.0f / FF) - mu * mu;
    const float rs  = rsqrtf(var + LN_EPS);
    float* o = Out + (size_t)row * FF;
    float v[3] = {v0, v1, v2};
    #pragma unroll
    for (int i = 0; i < 3; i++) {
        const int f = t + i * 128;
        o[f] = fmaxf((v[i] - mu) * rs * gam[f] + bet[f], 0.0f);
    }
}

__global__ __launch_bounds__(128) void ln_linear_kernel(
    const float* __restrict__ In, const float* __restrict__ gam,
    const float* __restrict__ bet, const float* __restrict__ lw,
    const float* __restrict__ lb, float* __restrict__ dur)
{
    const int row = blockIdx.x;
    const int t   = threadIdx.x;
    const float* p = In + (size_t)row * FF;
    float v0 = p[t], v1 = p[t + 128], v2 = p[t + 256];
    float2 r = block_reduce2(v0 + v1 + v2, v0 * v0 + v1 * v1 + v2 * v2);
    const float mu  = r.x * (1.0f / FF);
    const float var = r.y * (1.0f / FF) - mu * mu;
    const float rs  = rsqrtf(var + LN_EPS);
    float v[3] = {v0, v1, v2};
    float acc = 0.0f;
    #pragma unroll
    for (int i = 0; i < 3; i++) {
        const int f = t + i * 128;
        float h = fmaxf((v[i] - mu) * rs * gam[f] + bet[f], 0.0f);
        acc += h * lw[f];
    }
    float2 r2 = block_reduce2(acc, 0.0f);
    if (t == 0) dur[row] = fmaxf(r2.x + lb[0], 0.0f);
}

__global__ __launch_bounds__(512) void scan_kernel(const int* __restrict__ target)
{
    __shared__ int s[512];
    const int b = blockIdx.x, t = threadIdx.x;
    s[t] = target[b * LQ + t];
    __syncthreads();
    for (int off = 1; off < 512; off <<= 1) {
        int v = (t >= off) ? s[t - off] : 0;
        __syncthreads();
        s[t] += v;
        __syncthreads();
    }
    g_cum[b * LQ + t] = s[t];
}

// Expand: block = 4 frames x 96 threads (float4 lanes).
__global__ __launch_bounds__(384) void expand_kernel(
    const float* __restrict__ X, float* __restrict__ out, int M)
{
    const int tfr = blockIdx.x * 4 + threadIdx.y;
    const int b   = blockIdx.y;
    const int* cum = g_cum + b * LQ;
    float4* dst = (float4*)(out + ((size_t)b * M + tfr) * DD);
    const int total = cum[LQ - 1];
    if (tfr >= total) {
        dst[threadIdx.x] = make_float4(0.f, 0.f, 0.f, 0.f);
        return;
    }
    int lo = 0, hi = LQ;
    while (lo < hi) {
        int mid = (lo + hi) >> 1;
        if (cum[mid] <= tfr) lo = mid + 1; else hi = mid;
    }
    const int idx = min(lo, LQ - 1);
    const float4* src = (const float4*)(X + ((size_t)b * LQ + idx) * DD);
    dst[threadIdx.x] = src[threadIdx.x];
}

// ---------------------------------------------------------------------------
extern "C" void kernel_launch(void* const* d_in, const int* in_sizes, int n_in,
                              void* d_out, int out_size)
{
    const float* x     = (const float*)d_in[0];
    const float* c1_w  = (const float*)d_in[1];
    const float* c1_b  = (const float*)d_in[2];
    const float* ln1_g = (const float*)d_in[3];
    const float* ln1_b = (const float*)d_in[4];
    const float* c2_w  = (const float*)d_in[5];
    const float* c2_b  = (const float*)d_in[6];
    const float* ln2_g = (const float*)d_in[7];
    const float* ln2_b = (const float*)d_in[8];
    const float* lin_w = (const float*)d_in[9];
    const float* lin_b = (const float*)d_in[10];
    const int*   target= (const int*)d_in[11];

    const int M = (out_size - BB * LQ) / (BB * DD);

    float* buf1; cudaGetSymbolAddress((void**)&buf1, g_buf1);
    float* buf2; cudaGetSymbolAddress((void**)&buf2, g_buf2);
    float* w1r;  cudaGetSymbolAddress((void**)&w1r,  g_w1r);
    float* w2r;  cudaGetSymbolAddress((void**)&w2r,  g_w2r);

    float* out_expand = (float*)d_out;
    float* out_dur    = (float*)d_out + (size_t)BB * M * DD;

    dim3 gemm_grid(MROWS / 128, FF / 128);

    reorder_w_kernel<<<FF, 256>>>(c1_w, w1r);
    reorder_w_kernel<<<FF, 256>>>(c2_w, w2r);

    conv_mma_kernel<<<gemm_grid, 128>>>(x, w1r, c1_b, buf1);
    ln_relu_kernel<<<MROWS, 128>>>(buf1, ln1_g, ln1_b, buf2);
    conv_mma_kernel<<<gemm_grid, 128>>>(buf2, w2r, c2_b, buf1);
    ln_linear_kernel<<<MROWS, 128>>>(buf1, ln2_g, ln2_b, lin_w, lin_b, out_dur);

    scan_kernel<<<BB, 512>>>(target);
    expand_kernel<<<dim3(M / 4, BB), dim3(96, 4)>>>(x, out_expand, M);
}

// round 4
// speedup vs baseline: 1.4952x; 1.4952x over previous
#include <cuda_runtime.h>
#include <math.h>

#define BB   32
#define LQ   512
#define DD   384
#define FF   384
#define MROWS (BB*LQ)      // 16384
#define KDIM  (DD*3)       // 1152
#define LN_EPS 1e-5f

// Scratch (no allocations allowed).
__device__ float g_buf1[(size_t)MROWS * FF];   // conv outputs
__device__ float g_buf2[(size_t)MROWS * FF];   // ln_relu output (tf32, permuted)
__device__ float g_xp  [(size_t)MROWS * DD];   // x (tf32, permuted)
__device__ float g_w1r[(size_t)FF * KDIM];
__device__ float g_w2r[(size_t)FF * KDIM];
__device__ int   g_cum[BB * LQ];

// Pair-permutation within each 16-element K block: logical k and k+4 become
// adjacent physical slots, so fragments load with LDS.64.
//   j<4 -> 2j ; 4<=j<8 -> 2(j-4)+1 ; 8<=j<12 -> 2(j-8)+8 ; else 2(j-12)+9
__device__ __forceinline__ int perm16(int j)
{
    return (j < 4) ? 2 * j
         : (j < 8) ? 2 * (j - 4) + 1
         : (j < 12) ? 2 * (j - 8) + 8
                    : 2 * (j - 12) + 9;
}

__device__ __forceinline__ unsigned f2tf(float f)
{
    unsigned r;
    asm("cvt.rna.tf32.f32 %0, %1;" : "=r"(r) : "f"(f));
    return r;
}

// ---------------------------------------------------------------------------
// Prep x: tf32-round + permute d within 16-blocks.  xp[row][blk*16+perm(j)]
// ---------------------------------------------------------------------------
__global__ __launch_bounds__(256) void prep_x_kernel(
    const float* __restrict__ in, float* __restrict__ out)
{
    const int idx = blockIdx.x * 256 + threadIdx.x;   // < MROWS*DD
    const int row = idx / DD;
    const int col = idx - row * DD;
    const int blk = col >> 4, j = col & 15;
    out[(size_t)row * DD + (blk << 4) + perm16(j)] = __uint_as_float(f2tf(in[idx]));
}

// Reorder W: Wr[f][kseg*384 + blk*16 + perm(j)] = tf32(W[f][(blk*16+j)*3+kseg])
__global__ __launch_bounds__(256) void reorder_w_kernel(
    const float* __restrict__ W, float* __restrict__ Wr)
{
    const int f = blockIdx.x;
    for (int i = threadIdx.x; i < KDIM; i += 256) {
        const int kseg = i / DD;
        const int r    = i - kseg * DD;
        const int blk  = r >> 4, j = r & 15;
        const int dst  = kseg * DD + (blk << 4) + perm16(j);
        Wr[(size_t)f * KDIM + dst] =
            __uint_as_float(f2tf(W[(size_t)f * KDIM + (blk * 16 + j) * 3 + kseg]));
    }
}

__device__ __forceinline__ void mma_tf32(float c[4], const unsigned a[4],
                                         const unsigned b[2])
{
    asm volatile(
        "mma.sync.aligned.m16n8k8.row.col.f32.tf32.tf32.f32 "
        "{%0,%1,%2,%3}, {%4,%5,%6,%7}, {%8,%9}, {%0,%1,%2,%3};"
        : "+f"(c[0]), "+f"(c[1]), "+f"(c[2]), "+f"(c[3])
        : "r"(a[0]), "r"(a[1]), "r"(a[2]), "r"(a[3]), "r"(b[0]), "r"(b[1]));
}

__device__ __forceinline__ void cp16(unsigned dst, const float* src, bool p)
{
    const int sz = p ? 16 : 0;
    asm volatile("cp.async.cg.shared.global [%0], [%1], 16, %2;\n"
                 :: "r"(dst), "l"(src), "r"(sz));
}

// ---------------------------------------------------------------------------
// Conv-as-GEMM, tf32 mma.sync. CTA 128x128, BK=16, 256 threads, warps 2m x 4n
// (warp tile 64x32). cp.async double-buffer; inputs pre-rounded+pair-permuted
// so the loop is pure LDS.64 + MMA. Row stride 24 floats: 16B-aligned and
// conflict-free for the paired fragment loads.
// ---------------------------------------------------------------------------
__global__ __launch_bounds__(256, 2) void conv_mma_kernel(
    const float* __restrict__ Asrc, const float* __restrict__ Wr,
    const float* __restrict__ bias, float* __restrict__ Y)
{
    __shared__ float As[2][128][24];   // 12 KB per buffer
    __shared__ float Bs[2][128][24];

    const int m0 = blockIdx.x * 128;
    const int f0 = blockIdx.y * 128;
    const int t  = threadIdx.x;
    const int lane = t & 31, grp = lane >> 2, tig = lane & 3;
    const int warp = t >> 5;
    const int m_base = (warp & 1) * 64;
    const int n_base = (warp >> 1) * 32;

    // loader: each thread fills 2 A rows + 2 B rows, one 16B chunk each
    const int lrow = t >> 2;            // 0..63
    const int c4   = (t & 3) * 4;       // 0,4,8,12

    const int mA0 = m0 + lrow, mA1 = mA0 + 64;
    const int bA0 = mA0 >> 9, lA0 = mA0 & 511;
    const int bA1 = mA1 >> 9, lA1 = mA1 & 511;

    const unsigned aAd0 = (unsigned)__cvta_generic_to_shared(&As[0][lrow][c4]);
    const unsigned bAd0 = (unsigned)__cvta_generic_to_shared(&Bs[0][lrow][c4]);
    const unsigned BUFB = 128 * 24 * 4;       // bytes per buffer
    const unsigned ROW64 = 64 * 24 * 4;

    const float* wr0 = Wr + (size_t)(f0 + lrow) * KDIM + c4;
    const float* wr1 = Wr + (size_t)(f0 + lrow + 64) * KDIM + c4;

    float acc[4][4][4] = {};

    auto load_tile = [&](int it, int buf) {
        const int kk0  = it * 16;
        const int kseg = (kk0 >= 384) + (kk0 >= 768);
        const int off  = kk0 - kseg * DD + c4;
        const int l20  = lA0 + kseg - 1;
        const int l21  = lA1 + kseg - 1;
        const bool v0 = (l20 >= 0) & (l20 < LQ);
        const bool v1 = (l21 >= 0) & (l21 < LQ);
        const float* sa0 = Asrc + ((size_t)(bA0 << 9) + (v0 ? l20 : 0)) * DD + off;
        const float* sa1 = Asrc + ((size_t)(bA1 << 9) + (v1 ? l21 : 0)) * DD + off;
        cp16(aAd0 + buf * BUFB,         sa0, v0);
        cp16(aAd0 + buf * BUFB + ROW64, sa1, v1);
        cp16(bAd0 + buf * BUFB,         wr0 + kk0, true);
        cp16(bAd0 + buf * BUFB + ROW64, wr1 + kk0, true);
    };

    // prologue
    load_tile(0, 0);
    asm volatile("cp.async.commit_group;");
    asm volatile("cp.async.wait_group 0;");
    __syncthreads();

    const int NIT = KDIM / 16;   // 72
    for (int it = 0; it < NIT; ++it) {
        if (it + 1 < NIT) load_tile(it + 1, (it + 1) & 1);
        asm volatile("cp.async.commit_group;");

        const int buf = it & 1;
        #pragma unroll
        for (int ks = 0; ks < 2; ++ks) {
            const int pc = ks * 8 + 2 * tig;   // physical col of (k, k+4) pair
            float2 bf[4];
            #pragma unroll
            for (int nt = 0; nt < 4; ++nt)
                bf[nt] = *(const float2*)&Bs[buf][n_base + nt * 8 + grp][pc];
            #pragma unroll
            for (int mt = 0; mt < 4; ++mt) {
                const int ar = m_base + mt * 16 + grp;
                const float2 a02 = *(const float2*)&As[buf][ar][pc];
                const float2 a13 = *(const float2*)&As[buf][ar + 8][pc];
                const unsigned af[4] = {
                    __float_as_uint(a02.x), __float_as_uint(a13.x),
                    __float_as_uint(a02.y), __float_as_uint(a13.y) };
                #pragma unroll
                for (int nt = 0; nt < 4; ++nt) {
                    const unsigned bb[2] = { __float_as_uint(bf[nt].x),
                                             __float_as_uint(bf[nt].y) };
                    mma_tf32(acc[mt][nt], af, bb);
                }
            }
        }

        asm volatile("cp.async.wait_group 0;");
        __syncthreads();
    }

    // epilogue: bias + store (fp32)
    #pragma unroll
    for (int mt = 0; mt < 4; ++mt) {
        const int mrow = m0 + m_base + mt * 16 + grp;
        #pragma unroll
        for (int nt = 0; nt < 4; ++nt) {
            const int fc = f0 + n_base + nt * 8 + 2 * tig;
            const float b0v = bias[fc], b1v = bias[fc + 1];
            float2 r0 = make_float2(acc[mt][nt][0] + b0v, acc[mt][nt][1] + b1v);
            float2 r1 = make_float2(acc[mt][nt][2] + b0v, acc[mt][nt][3] + b1v);
            *(float2*)&Y[(size_t)mrow * FF + fc] = r0;
            *(float2*)&Y[(size_t)(mrow + 8) * FF + fc] = r1;
        }
    }
}

// ---------------------------------------------------------------------------
__device__ __forceinline__ float2 block_reduce2(float s, float q)
{
    __shared__ float sh[8];
    __syncthreads();
    const int lane = threadIdx.x & 31;
    const int w    = threadIdx.x >> 5;
    #pragma unroll
    for (int o = 16; o > 0; o >>= 1) {
        s += __shfl_down_sync(0xffffffffu, s, o);
        q += __shfl_down_sync(0xffffffffu, q, o);
    }
    if (lane == 0) { sh[w] = s; sh[4 + w] = q; }
    __syncthreads();
    if (threadIdx.x == 0) {
        sh[0] = sh[0] + sh[1] + sh[2] + sh[3];
        sh[4] = sh[4] + sh[5] + sh[6] + sh[7];
    }
    __syncthreads();
    return make_float2(sh[0], sh[4]);
}

// LN+ReLU; output tf32-rounded and pair-permuted (feeds conv2's A path).
__global__ __launch_bounds__(128) void ln_relu_kernel(
    const float* __restrict__ In, const float* __restrict__ gam,
    const float* __restrict__ bet, float* __restrict__ Out)
{
    const int row = blockIdx.x;
    const int t   = threadIdx.x;
    const float* p = In + (size_t)row * FF;
    float v0 = p[t], v1 = p[t + 128], v2 = p[t + 256];
    float2 r = block_reduce2(v0 + v1 + v2, v0 * v0 + v1 * v1 + v2 * v2);
    const float mu  = r.x * (1.0f / FF);
    const float var = r.y * (1.0f / FF) - mu * mu;
    const float rs  = rsqrtf(var + LN_EPS);
    float* o = Out + (size_t)row * FF;
    float v[3] = {v0, v1, v2};
    #pragma unroll
    for (int i = 0; i < 3; i++) {
        const int f = t + i * 128;
        const float h = fmaxf((v[i] - mu) * rs * gam[f] + bet[f], 0.0f);
        const int blk = f >> 4, j = f & 15;
        o[(blk << 4) + perm16(j)] = __uint_as_float(f2tf(h));
    }
}

__global__ __launch_bounds__(128) void ln_linear_kernel(
    const float* __restrict__ In, const float* __restrict__ gam,
    const float* __restrict__ bet, const float* __restrict__ lw,
    const float* __restrict__ lb, float* __restrict__ dur)
{
    const int row = blockIdx.x;
    const int t   = threadIdx.x;
    const float* p = In + (size_t)row * FF;
    float v0 = p[t], v1 = p[t + 128], v2 = p[t + 256];
    float2 r = block_reduce2(v0 + v1 + v2, v0 * v0 + v1 * v1 + v2 * v2);
    const float mu  = r.x * (1.0f / FF);
    const float var = r.y * (1.0f / FF) - mu * mu;
    const float rs  = rsqrtf(var + LN_EPS);
    float v[3] = {v0, v1, v2};
    float acc = 0.0f;
    #pragma unroll
    for (int i = 0; i < 3; i++) {
        const int f = t + i * 128;
        float h = fmaxf((v[i] - mu) * rs * gam[f] + bet[f], 0.0f);
        acc += h * lw[f];
    }
    float2 r2 = block_reduce2(acc, 0.0f);
    if (t == 0) dur[row] = fmaxf(r2.x + lb[0], 0.0f);
}

__global__ __launch_bounds__(512) void scan_kernel(const int* __restrict__ target)
{
    __shared__ int s[512];
    const int b = blockIdx.x, t = threadIdx.x;
    s[t] = target[b * LQ + t];
    __syncthreads();
    for (int off = 1; off < 512; off <<= 1) {
        int v = (t >= off) ? s[t - off] : 0;
        __syncthreads();
        s[t] += v;
        __syncthreads();
    }
    g_cum[b * LQ + t] = s[t];
}

// Expand: block = 4 frames x 96 threads (float4 lanes). Reads ORIGINAL x.
__global__ __launch_bounds__(384) void expand_kernel(
    const float* __restrict__ X, float* __restrict__ out, int M)
{
    const int tfr = blockIdx.x * 4 + threadIdx.y;
    const int b   = blockIdx.y;
    const int* cum = g_cum + b * LQ;
    float4* dst = (float4*)(out + ((size_t)b * M + tfr) * DD);
    const int total = cum[LQ - 1];
    if (tfr >= total) {
        dst[threadIdx.x] = make_float4(0.f, 0.f, 0.f, 0.f);
        return;
    }
    int lo = 0, hi = LQ;
    while (lo < hi) {
        int mid = (lo + hi) >> 1;
        if (cum[mid] <= tfr) lo = mid + 1; else hi = mid;
    }
    const int idx = min(lo, LQ - 1);
    const float4* src = (const float4*)(X + ((size_t)b * LQ + idx) * DD);
    dst[threadIdx.x] = src[threadIdx.x];
}

// ---------------------------------------------------------------------------
extern "C" void kernel_launch(void* const* d_in, const int* in_sizes, int n_in,
                              void* d_out, int out_size)
{
    const float* x     = (const float*)d_in[0];
    const float* c1_w  = (const float*)d_in[1];
    const float* c1_b  = (const float*)d_in[2];
    const float* ln1_g = (const float*)d_in[3];
    const float* ln1_b = (const float*)d_in[4];
    const float* c2_w  = (const float*)d_in[5];
    const float* c2_b  = (const float*)d_in[6];
    const float* ln2_g = (const float*)d_in[7];
    const float* ln2_b = (const float*)d_in[8];
    const float* lin_w = (const float*)d_in[9];
    const float* lin_b = (const float*)d_in[10];
    const int*   target= (const int*)d_in[11];

    const int M = (out_size - BB * LQ) / (BB * DD);

    float* buf1; cudaGetSymbolAddress((void**)&buf1, g_buf1);
    float* buf2; cudaGetSymbolAddress((void**)&buf2, g_buf2);
    float* xp;   cudaGetSymbolAddress((void**)&xp,   g_xp);
    float* w1r;  cudaGetSymbolAddress((void**)&w1r,  g_w1r);
    float* w2r;  cudaGetSymbolAddress((void**)&w2r,  g_w2r);

    float* out_expand = (float*)d_out;
    float* out_dur    = (float*)d_out + (size_t)BB * M * DD;

    dim3 gemm_grid(MROWS / 128, FF / 128);

    // Prep (rounding + permutation once, outside the hot loops)
    prep_x_kernel<<<MROWS * DD / 256, 256>>>(x, xp);
    reorder_w_kernel<<<FF, 256>>>(c1_w, w1r);
    reorder_w_kernel<<<FF, 256>>>(c2_w, w2r);

    conv_mma_kernel<<<gemm_grid, 256>>>(xp, w1r, c1_b, buf1);
    ln_relu_kernel<<<MROWS, 128>>>(buf1, ln1_g, ln1_b, buf2);
    conv_mma_kernel<<<gemm_grid, 256>>>(buf2, w2r, c2_b, buf1);
    ln_linear_kernel<<<MROWS, 128>>>(buf1, ln2_g, ln2_b, lin_w, lin_b, out_dur);

    scan_kernel<<<BB, 512>>>(target);
    expand_kernel<<<dim3(M / 4, BB), dim3(96, 4)>>>(x, out_expand, M);
}

// round 5
// speedup vs baseline: 1.5224x; 1.0182x over previous
#include <cuda_runtime.h>
#include <math.h>

#define BB   32
#define LQ   512
#define DD   384
#define FF   384
#define MROWS (BB*LQ)      // 16384
#define KDIM  (DD*3)       // 1152
#define LN_EPS 1e-5f
#define STAGES 3
#define ROWSTRIDE 24       // floats per smem row (conflict-free, 16B aligned)

// Scratch (no allocations allowed).
__device__ float g_buf1[(size_t)MROWS * FF];
__device__ float g_buf2[(size_t)MROWS * FF];
__device__ float g_xp  [(size_t)MROWS * DD];
__device__ float g_w1r[(size_t)FF * KDIM];
__device__ float g_w2r[(size_t)FF * KDIM];
__device__ int   g_cum[BB * LQ];

// Pair-permutation within each 16-element K block (k and k+4 adjacent -> LDS.64)
__device__ __forceinline__ int perm16(int j)
{
    return (j < 4) ? 2 * j
         : (j < 8) ? 2 * (j - 4) + 1
         : (j < 12) ? 2 * (j - 8) + 8
                    : 2 * (j - 12) + 9;
}

__device__ __forceinline__ unsigned f2tf(float f)
{
    unsigned r;
    asm("cvt.rna.tf32.f32 %0, %1;" : "=r"(r) : "f"(f));
    return r;
}

__global__ __launch_bounds__(256) void prep_x_kernel(
    const float* __restrict__ in, float* __restrict__ out)
{
    const int idx = blockIdx.x * 256 + threadIdx.x;
    const int row = idx / DD;
    const int col = idx - row * DD;
    const int blk = col >> 4, j = col & 15;
    out[(size_t)row * DD + (blk << 4) + perm16(j)] = __uint_as_float(f2tf(in[idx]));
}

__global__ __launch_bounds__(256) void reorder_w_kernel(
    const float* __restrict__ W, float* __restrict__ Wr)
{
    const int f = blockIdx.x;
    for (int i = threadIdx.x; i < KDIM; i += 256) {
        const int kseg = i / DD;
        const int r    = i - kseg * DD;
        const int blk  = r >> 4, j = r & 15;
        const int dst  = kseg * DD + (blk << 4) + perm16(j);
        Wr[(size_t)f * KDIM + dst] =
            __uint_as_float(f2tf(W[(size_t)f * KDIM + (blk * 16 + j) * 3 + kseg]));
    }
}

__device__ __forceinline__ void mma_tf32(float c[4], const unsigned a[4],
                                         const unsigned b[2])
{
    asm volatile(
        "mma.sync.aligned.m16n8k8.row.col.f32.tf32.tf32.f32 "
        "{%0,%1,%2,%3}, {%4,%5,%6,%7}, {%8,%9}, {%0,%1,%2,%3};"
        : "+f"(c[0]), "+f"(c[1]), "+f"(c[2]), "+f"(c[3])
        : "r"(a[0]), "r"(a[1]), "r"(a[2]), "r"(a[3]), "r"(b[0]), "r"(b[1]));
}

__device__ __forceinline__ void cp16(unsigned dst, const float* src, bool p)
{
    const int sz = p ? 16 : 0;
    asm volatile("cp.async.cg.shared.global [%0], [%1], 16, %2;\n"
                 :: "r"(dst), "l"(src), "r"(sz));
}

// ---------------------------------------------------------------------------
// Conv-as-GEMM, tf32 mma.sync. CTA 128x128, BK=16, 256 threads, warps 2m x 4n.
// 3-stage cp.async pipeline (wait_group 1): each load has a full iteration of
// slack. Inputs pre-rounded + pair-permuted -> loop is pure LDS.64 + MMA.
// ---------------------------------------------------------------------------
__global__ __launch_bounds__(256, 2) void conv_mma_kernel(
    const float* __restrict__ Asrc, const float* __restrict__ Wr,
    const float* __restrict__ bias, float* __restrict__ Y)
{
    extern __shared__ float sm[];
    float* As = sm;                              // [STAGES][128][24]
    float* Bs = sm + STAGES * 128 * ROWSTRIDE;   // [STAGES][128][24]

    const int m0 = blockIdx.x * 128;
    const int f0 = blockIdx.y * 128;
    const int t  = threadIdx.x;
    const int lane = t & 31, grp = lane >> 2, tig = lane & 3;
    const int warp = t >> 5;
    const int m_base = (warp & 1) * 64;
    const int n_base = (warp >> 1) * 32;

    const int lrow = t >> 2;            // 0..63
    const int c4   = (t & 3) * 4;       // 0,4,8,12

    const int mA0 = m0 + lrow, mA1 = mA0 + 64;
    const int bA0 = mA0 >> 9, lA0 = mA0 & 511;
    const int bA1 = mA1 >> 9, lA1 = mA1 & 511;

    const unsigned aAd0 = (unsigned)__cvta_generic_to_shared(&As[lrow * ROWSTRIDE + c4]);
    const unsigned bAd0 = (unsigned)__cvta_generic_to_shared(&Bs[lrow * ROWSTRIDE + c4]);
    const unsigned STB   = 128 * ROWSTRIDE * 4;   // bytes per stage
    const unsigned ROW64 = 64 * ROWSTRIDE * 4;

    const float* wr0 = Wr + (size_t)(f0 + lrow) * KDIM + c4;
    const float* wr1 = Wr + (size_t)(f0 + lrow + 64) * KDIM + c4;

    float acc[4][4][4] = {};

    auto load_tile = [&](int it, int st) {
        const int kk0  = it * 16;
        const int kseg = (kk0 >= 384) + (kk0 >= 768);
        const int off  = kk0 - kseg * DD + c4;
        const int l20  = lA0 + kseg - 1;
        const int l21  = lA1 + kseg - 1;
        const bool v0 = (l20 >= 0) & (l20 < LQ);
        const bool v1 = (l21 >= 0) & (l21 < LQ);
        const float* sa0 = Asrc + ((size_t)(bA0 << 9) + (v0 ? l20 : 0)) * DD + off;
        const float* sa1 = Asrc + ((size_t)(bA1 << 9) + (v1 ? l21 : 0)) * DD + off;
        cp16(aAd0 + st * STB,         sa0, v0);
        cp16(aAd0 + st * STB + ROW64, sa1, v1);
        cp16(bAd0 + st * STB,         wr0 + kk0, true);
        cp16(bAd0 + st * STB + ROW64, wr1 + kk0, true);
    };

    // prologue: stages 0,1 in flight
    load_tile(0, 0);
    asm volatile("cp.async.commit_group;");
    load_tile(1, 1);
    asm volatile("cp.async.commit_group;");
    asm volatile("cp.async.wait_group 1;");   // stage 0 ready
    __syncthreads();

    const int NIT = KDIM / 16;   // 72
    int st_next = 2, buf = 0;
    for (int it = 0; it < NIT; ++it) {
        // issue load for stage it+2 (writes buffer last read in iter it-1)
        if (it + 2 < NIT) load_tile(it + 2, st_next);
        asm volatile("cp.async.commit_group;");
        if (++st_next == STAGES) st_next = 0;

        const float* Ab = As + buf * 128 * ROWSTRIDE;
        const float* Bb = Bs + buf * 128 * ROWSTRIDE;
        #pragma unroll
        for (int ks = 0; ks < 2; ++ks) {
            const int pc = ks * 8 + 2 * tig;
            float2 bf[4];
            #pragma unroll
            for (int nt = 0; nt < 4; ++nt)
                bf[nt] = *(const float2*)&Bb[(n_base + nt * 8 + grp) * ROWSTRIDE + pc];
            #pragma unroll
            for (int mt = 0; mt < 4; ++mt) {
                const int ar = m_base + mt * 16 + grp;
                const float2 a02 = *(const float2*)&Ab[ar * ROWSTRIDE + pc];
                const float2 a13 = *(const float2*)&Ab[(ar + 8) * ROWSTRIDE + pc];
                const unsigned af[4] = {
                    __float_as_uint(a02.x), __float_as_uint(a13.x),
                    __float_as_uint(a02.y), __float_as_uint(a13.y) };
                #pragma unroll
                for (int nt = 0; nt < 4; ++nt) {
                    const unsigned bb[2] = { __float_as_uint(bf[nt].x),
                                             __float_as_uint(bf[nt].y) };
                    mma_tf32(acc[mt][nt], af, bb);
                }
            }
        }
        if (++buf == STAGES) buf = 0;

        asm volatile("cp.async.wait_group 1;");   // next stage ready
        __syncthreads();
    }

    // epilogue: bias + store
    #pragma unroll
    for (int mt = 0; mt < 4; ++mt) {
        const int mrow = m0 + m_base + mt * 16 + grp;
        #pragma unroll
        for (int nt = 0; nt < 4; ++nt) {
            const int fc = f0 + n_base + nt * 8 + 2 * tig;
            const float b0v = bias[fc], b1v = bias[fc + 1];
            float2 r0 = make_float2(acc[mt][nt][0] + b0v, acc[mt][nt][1] + b1v);
            float2 r1 = make_float2(acc[mt][nt][2] + b0v, acc[mt][nt][3] + b1v);
            *(float2*)&Y[(size_t)mrow * FF + fc] = r0;
            *(float2*)&Y[(size_t)(mrow + 8) * FF + fc] = r1;
        }
    }
}

// ---------------------------------------------------------------------------
__device__ __forceinline__ float2 block_reduce2(float s, float q)
{
    __shared__ float sh[8];
    __syncthreads();
    const int lane = threadIdx.x & 31;
    const int w    = threadIdx.x >> 5;
    #pragma unroll
    for (int o = 16; o > 0; o >>= 1) {
        s += __shfl_down_sync(0xffffffffu, s, o);
        q += __shfl_down_sync(0xffffffffu, q, o);
    }
    if (lane == 0) { sh[w] = s; sh[4 + w] = q; }
    __syncthreads();
    if (threadIdx.x == 0) {
        sh[0] = sh[0] + sh[1] + sh[2] + sh[3];
        sh[4] = sh[4] + sh[5] + sh[6] + sh[7];
    }
    __syncthreads();
    return make_float2(sh[0], sh[4]);
}

__global__ __launch_bounds__(128) void ln_relu_kernel(
    const float* __restrict__ In, const float* __restrict__ gam,
    const float* __restrict__ bet, float* __restrict__ Out)
{
    const int row = blockIdx.x;
    const int t   = threadIdx.x;
    const float* p = In + (size_t)row * FF;
    float v0 = p[t], v1 = p[t + 128], v2 = p[t + 256];
    float2 r = block_reduce2(v0 + v1 + v2, v0 * v0 + v1 * v1 + v2 * v2);
    const float mu  = r.x * (1.0f / FF);
    const float var = r.y * (1.0f / FF) - mu * mu;
    const float rs  = rsqrtf(var + LN_EPS);
    float* o = Out + (size_t)row * FF;
    float v[3] = {v0, v1, v2};
    #pragma unroll
    for (int i = 0; i < 3; i++) {
        const int f = t + i * 128;
        const float h = fmaxf((v[i] - mu) * rs * gam[f] + bet[f], 0.0f);
        const int blk = f >> 4, j = f & 15;
        o[(blk << 4) + perm16(j)] = __uint_as_float(f2tf(h));
    }
}

__global__ __launch_bounds__(128) void ln_linear_kernel(
    const float* __restrict__ In, const float* __restrict__ gam,
    const float* __restrict__ bet, const float* __restrict__ lw,
    const float* __restrict__ lb, float* __restrict__ dur)
{
    const int row = blockIdx.x;
    const int t   = threadIdx.x;
    const float* p = In + (size_t)row * FF;
    float v0 = p[t], v1 = p[t + 128], v2 = p[t + 256];
    float2 r = block_reduce2(v0 + v1 + v2, v0 * v0 + v1 * v1 + v2 * v2);
    const float mu  = r.x * (1.0f / FF);
    const float var = r.y * (1.0f / FF) - mu * mu;
    const float rs  = rsqrtf(var + LN_EPS);
    float v[3] = {v0, v1, v2};
    float acc = 0.0f;
    #pragma unroll
    for (int i = 0; i < 3; i++) {
        const int f = t + i * 128;
        float h = fmaxf((v[i] - mu) * rs * gam[f] + bet[f], 0.0f);
        acc += h * lw[f];
    }
    float2 r2 = block_reduce2(acc, 0.0f);
    if (t == 0) dur[row] = fmaxf(r2.x + lb[0], 0.0f);
}

__global__ __launch_bounds__(512) void scan_kernel(const int* __restrict__ target)
{
    __shared__ int s[512];
    const int b = blockIdx.x, t = threadIdx.x;
    s[t] = target[b * LQ + t];
    __syncthreads();
    for (int off = 1; off < 512; off <<= 1) {
        int v = (t >= off) ? s[t - off] : 0;
        __syncthreads();
        s[t] += v;
        __syncthreads();
    }
    g_cum[b * LQ + t] = s[t];
}

__global__ __launch_bounds__(384) void expand_kernel(
    const float* __restrict__ X, float* __restrict__ out, int M)
{
    const int tfr = blockIdx.x * 4 + threadIdx.y;
    const int b   = blockIdx.y;
    const int* cum = g_cum + b * LQ;
    float4* dst = (float4*)(out + ((size_t)b * M + tfr) * DD);
    const int total = cum[LQ - 1];
    if (tfr >= total) {
        dst[threadIdx.x] = make_float4(0.f, 0.f, 0.f, 0.f);
        return;
    }
    int lo = 0, hi = LQ;
    while (lo < hi) {
        int mid = (lo + hi) >> 1;
        if (cum[mid] <= tfr) lo = mid + 1; else hi = mid;
    }
    const int idx = min(lo, LQ - 1);
    const float4* src = (const float4*)(X + ((size_t)b * LQ + idx) * DD);
    dst[threadIdx.x] = src[threadIdx.x];
}

// ---------------------------------------------------------------------------
extern "C" void kernel_launch(void* const* d_in, const int* in_sizes, int n_in,
                              void* d_out, int out_size)
{
    const float* x     = (const float*)d_in[0];
    const float* c1_w  = (const float*)d_in[1];
    const float* c1_b  = (const float*)d_in[2];
    const float* ln1_g = (const float*)d_in[3];
    const float* ln1_b = (const float*)d_in[4];
    const float* c2_w  = (const float*)d_in[5];
    const float* c2_b  = (const float*)d_in[6];
    const float* ln2_g = (const float*)d_in[7];
    const float* ln2_b = (const float*)d_in[8];
    const float* lin_w = (const float*)d_in[9];
    const float* lin_b = (const float*)d_in[10];
    const int*   target= (const int*)d_in[11];

    const int M = (out_size - BB * LQ) / (BB * DD);

    float* buf1; cudaGetSymbolAddress((void**)&buf1, g_buf1);
    float* buf2; cudaGetSymbolAddress((void**)&buf2, g_buf2);
    float* xp;   cudaGetSymbolAddress((void**)&xp,   g_xp);
    float* w1r;  cudaGetSymbolAddress((void**)&w1r,  g_w1r);
    float* w2r;  cudaGetSymbolAddress((void**)&w2r,  g_w2r);

    float* out_expand = (float*)d_out;
    float* out_dur    = (float*)d_out + (size_t)BB * M * DD;

    const int smem_bytes = 2 * STAGES * 128 * ROWSTRIDE * 4;  // 73728
    cudaFuncSetAttribute(conv_mma_kernel,
                         cudaFuncAttributeMaxDynamicSharedMemorySize, smem_bytes);

    // Fork: scan+expand are independent of the predictor chain.
    cudaStream_t s2;
    cudaStreamCreateWithFlags(&s2, cudaStreamNonBlocking);
    cudaEvent_t ev_fork, ev_join;
    cudaEventCreateWithFlags(&ev_fork, cudaEventDisableTiming);
    cudaEventCreateWithFlags(&ev_join, cudaEventDisableTiming);

    cudaEventRecord(ev_fork, 0);
    cudaStreamWaitEvent(s2, ev_fork, 0);
    scan_kernel<<<BB, 512, 0, s2>>>(target);
    expand_kernel<<<dim3(M / 4, BB), dim3(96, 4), 0, s2>>>(x, out_expand, M);
    cudaEventRecord(ev_join, s2);

    // Predictor chain on the captured default stream
    dim3 gemm_grid(MROWS / 128, FF / 128);
    prep_x_kernel<<<MROWS * DD / 256, 256>>>(x, xp);
    reorder_w_kernel<<<FF, 256>>>(c1_w, w1r);
    reorder_w_kernel<<<FF, 256>>>(c2_w, w2r);
    conv_mma_kernel<<<gemm_grid, 256, smem_bytes>>>(xp, w1r, c1_b, buf1);
    ln_relu_kernel<<<MROWS, 128>>>(buf1, ln1_g, ln1_b, buf2);
    conv_mma_kernel<<<gemm_grid, 256, smem_bytes>>>(buf2, w2r, c2_b, buf1);
    ln_linear_kernel<<<MROWS, 128>>>(buf1, ln2_g, ln2_b, lin_w, lin_b, out_dur);

    // Join
    cudaStreamWaitEvent(0, ev_join, 0);
}